// round 17
// baseline (speedup 1.0000x reference)
#include <cuda_runtime.h>
#include <cuda_fp16.h>
#include <stdint.h>
#include <math.h>

#define DIM 256
#define NGATES 46
#define NROWS 32768
#define BM 32
#define GRID 148
#define UNITS (NROWS / BM)              // 1024
#define NMY_THRESH (UNITS - 6 * GRID)   // 136: ctas < this do 7 units, else 6
#define THREADS 512

// ---- GEMM smem layout ----
#define SB_OFF 0                    // 2 x 65536 (B chunk: 512 n-rows x 128B, swizzled)
#define SA16_OFF 131072             // 16384 (A unit fp16: 32 rows x 512B, swizzled)
#define SA32_OFF 147456             // 32768 (A unit fp32 staging: 32 rows x 1024B)
#define SYP_OFF 180224              // float[8][32][8] = 8192
#define SYO_OFF 188416              // float[256] = 1024
#define SMEM_TOT 189440

// Scratch (device globals — no allocation)
__device__ __half g_Wh[512 * 256];  // [c][d] fp16(W), c<256:Re, c>=256:Im

struct Cplx { float x, y; };
__device__ __forceinline__ Cplx cmul(Cplx a, Cplx b) { return {a.x*b.x - a.y*b.y, a.x*b.y + a.y*b.x}; }
__device__ __forceinline__ Cplx cadd(Cplx a, Cplx b) { return {a.x + b.x, a.y + b.y}; }

// ---------------- build_U: 32 blocks x 256 thr, one warp per column, state in registers ----------------
__global__ void build_kernel(const float* __restrict__ th1,
                             const float* __restrict__ th2,
                             const float* __restrict__ th3) {
    __shared__ Cplx M[NGATES][4];
    const int tid = threadIdx.x;
    const int wid = tid >> 5, l = tid & 31;
    const int col = blockIdx.x * 8 + wid;

    if (tid < NGATES) {
        int g = tid, a, r;
        if (g < 16)      { a = 0; r = g; }
        else if (g < 30) { a = 1; r = g - 16; }
        else             { a = 2; r = g - 30; }
        const float* th = (a == 0) ? th1 : ((a == 1) ? th2 : th3);
        float t1 = th[r*3 + 0], t2 = th[r*3 + 1], t3 = th[r*3 + 2];
        float cx, sx, cy, sy, cz, szv;
        sincosf(0.5f * t1, &sx, &cx);
        sincosf(0.5f * t2, &sy, &cy);
        sincosf(0.5f * t3, &szv, &cz);
        Cplx A00 = { cy*cx,  sy*sx};
        Cplx A01 = {-sy*cx, -cy*sx};
        Cplx A10 = { sy*cx, -cy*sx};
        Cplx A11 = { cy*cx, -sy*sx};
        Cplx em = {cz, -szv}, ep = {cz, szv};
        M[tid][0] = cmul(em, A00);
        M[tid][1] = cmul(em, A01);
        M[tid][2] = cmul(ep, A10);
        M[tid][3] = cmul(ep, A11);
    }
    __syncthreads();

    // state: v[j] = amp(j*32 + l); amp-index bit b == qubit b (0..4 lane, 5..7 reg)
    float2 v[8];
#pragma unroll
    for (int j = 0; j < 8; j++)
        v[j] = make_float2((j * 32 + l) == col ? 1.0f : 0.0f, 0.0f);

    const int nqs[3] = {8, 7, 8};
    int g = 0;
    for (int a = 0; a < 3; a++) {
        const int nq = nqs[a];
        for (int d = 0; d < 2; d++) {
            // fused Rz*Ry*Rx per qubit
#pragma unroll
            for (int q = 0; q < 8; q++) {
                if (q >= nq) continue;
                Cplx m00 = M[g][0], m01 = M[g][1], m10 = M[g][2], m11 = M[g][3];
                g++;
                if (q < 5) {
                    const int myBit = (l >> q) & 1;
#pragma unroll
                    for (int j = 0; j < 8; j++) {
                        float px = __shfl_xor_sync(0xffffffffu, v[j].x, 1 << q);
                        float py = __shfl_xor_sync(0xffffffffu, v[j].y, 1 << q);
                        Cplx own = {v[j].x, v[j].y}, par = {px, py};
                        Cplx a0 = myBit ? par : own;
                        Cplx a1 = myBit ? own : par;
                        Cplx mA = myBit ? m10 : m00;
                        Cplx mB = myBit ? m11 : m01;
                        Cplx r = cadd(cmul(mA, a0), cmul(mB, a1));
                        v[j] = make_float2(r.x, r.y);
                    }
                } else {
                    const int qb = q - 5, step = 1 << qb;
#pragma unroll
                    for (int j = 0; j < 8; j++) {
                        if ((j >> qb) & 1) continue;
                        int j1 = j + step;
                        Cplx a0 = {v[j].x, v[j].y}, a1 = {v[j1].x, v[j1].y};
                        Cplx r0 = cadd(cmul(m00, a0), cmul(m01, a1));
                        Cplx r1 = cadd(cmul(m10, a0), cmul(m11, a1));
                        v[j]  = make_float2(r0.x, r0.y);
                        v[j1] = make_float2(r1.x, r1.y);
                    }
                }
            }
            // CX chain: control q, target q+1 (swap target pair where ctrl=1)
#pragma unroll
            for (int q = 0; q < 7; q++) {
                if (q >= nq - 1) continue;
                if (q <= 3) {
                    const int ctrl = (l >> q) & 1;
#pragma unroll
                    for (int j = 0; j < 8; j++) {
                        float px = __shfl_xor_sync(0xffffffffu, v[j].x, 1 << (q + 1));
                        float py = __shfl_xor_sync(0xffffffffu, v[j].y, 1 << (q + 1));
                        if (ctrl) { v[j].x = px; v[j].y = py; }
                    }
                } else if (q == 4) {
                    if ((l >> 4) & 1) {
#pragma unroll
                        for (int j0 = 0; j0 < 8; j0 += 2) {
                            float2 t = v[j0]; v[j0] = v[j0 + 1]; v[j0 + 1] = t;
                        }
                    }
                } else if (q == 5) {   // ctrl = reg bit0, tgt = reg bit1
                    float2 t = v[1]; v[1] = v[3]; v[3] = t;
                    t = v[5]; v[5] = v[7]; v[7] = t;
                } else {               // q==6: ctrl = reg bit1, tgt = reg bit2
                    float2 t = v[2]; v[2] = v[6]; v[6] = t;
                    t = v[3]; v[3] = v[7]; v[7] = t;
                }
            }
        }
    }
    // W[c=k][col] = Re U[k][col], W[256+k][col] = Im — plain fp16
#pragma unroll
    for (int j = 0; j < 8; j++) {
        int k = j * 32 + l;
        g_Wh[(size_t)k * 256 + col]         = __float2half_rn(v[j].x);
        g_Wh[(size_t)(256 + k) * 256 + col] = __float2half_rn(v[j].y);
    }
}

// ---------------- persistent GEMM (fused X fp32->fp16 conversion) + epilogue ----------------
__device__ __forceinline__ void cpa16(unsigned int d, const void* s) {
    asm volatile("cp.async.cg.shared.global [%0], [%1], 16;\n" :: "r"(d), "l"(s));
}
#define CP_COMMIT() asm volatile("cp.async.commit_group;\n" ::: "memory")
#define CP_WAIT(N)  asm volatile("cp.async.wait_group %0;\n" :: "n"(N) : "memory")

#define LDSM4(R0,R1,R2,R3,ADDR) \
    asm volatile("ldmatrix.sync.aligned.m8n8.x4.shared.b16 {%0,%1,%2,%3}, [%4];" \
        : "=r"(R0), "=r"(R1), "=r"(R2), "=r"(R3) : "r"(ADDR))

#define MMA16816(C, A, B0, B1) \
    asm volatile("mma.sync.aligned.m16n8k16.row.col.f32.f16.f16.f32 " \
        "{%0,%1,%2,%3},{%4,%5,%6,%7},{%8,%9},{%0,%1,%2,%3};" \
        : "+f"((C)[0]), "+f"((C)[1]), "+f"((C)[2]), "+f"((C)[3]) \
        : "r"((A)[0]), "r"((A)[1]), "r"((A)[2]), "r"((A)[3]), "r"(B0), "r"(B1))

// B chunk ci (0..3): 512 n-rows x 64 k halfs (128B rows), XOR-swizzled 16B units
__device__ __forceinline__ void loadB(unsigned int sb, int tid, int buf, int ci) {
    unsigned int dst = sb + SB_OFF + buf * 65536;
    const __half* src = &g_Wh[ci * 64];
#pragma unroll
    for (int p = 0; p < 8; p++) {
        int u = tid + p * THREADS;
        int n = u >> 3, k = u & 7;
        cpa16(dst + n * 128 + (((unsigned)(k ^ (n & 7))) << 4),
              src + (size_t)n * 256 + k * 8);
    }
}
// A staging: 32 rows x 1024B fp32, plain layout
__device__ __forceinline__ void loadA32(unsigned int sb, int tid, const float* x, int unit) {
    unsigned int dst = sb + SA32_OFF;
    const float* src = x + (size_t)unit * 32 * 256;
#pragma unroll
    for (int p = 0; p < 4; p++) {
        int u = tid + p * THREADS;
        int r = u >> 6, c = u & 63;
        cpa16(dst + r * 1024 + c * 16, src + (size_t)r * 256 + c * 4);
    }
}
// convert staging fp32 -> swizzled fp16 A tile (2 x 16B units per thread)
__device__ __forceinline__ void convertA(char* smem, int tid) {
#pragma unroll
    for (int i = 0; i < 2; i++) {
        int u = tid * 2 + i;
        int r = u >> 5, k16 = u & 31;
        const float4* s4 = reinterpret_cast<const float4*>(smem + SA32_OFF + r * 1024 + k16 * 32);
        float4 f0 = s4[0], f1 = s4[1];
        __half2 h0 = __floats2half2_rn(f0.x, f0.y), h1 = __floats2half2_rn(f0.z, f0.w);
        __half2 h2 = __floats2half2_rn(f1.x, f1.y), h3 = __floats2half2_rn(f1.z, f1.w);
        uint4 o;
        o.x = *reinterpret_cast<uint32_t*>(&h0);
        o.y = *reinterpret_cast<uint32_t*>(&h1);
        o.z = *reinterpret_cast<uint32_t*>(&h2);
        o.w = *reinterpret_cast<uint32_t*>(&h3);
        *reinterpret_cast<uint4*>(smem + SA16_OFF + r * 512 + (((unsigned)(k16 ^ (r & 7))) << 4)) = o;
    }
}

__global__ __launch_bounds__(THREADS, 1)
void pqc_gemm_kernel(const float* __restrict__ x, float* __restrict__ out) {
    extern __shared__ char smem[];
    float* ypart = reinterpret_cast<float*>(smem + SYP_OFF);  // [8 wn][32 r][8 ob]
    float* yout  = reinterpret_cast<float*>(smem + SYO_OFF);  // [32][8]

    const int tid = threadIdx.x;
    const int l = tid & 31;
    const int wid = tid >> 5;
    const int wm = wid & 1;        // 16-row group
    const int wn = wid >> 1;       // 64-col group (0..7 over N=512)
    const int cta = blockIdx.x;

    unsigned int sb;
    asm("{ .reg .u64 t; cvta.to.shared.u64 t, %1; cvt.u32.u64 %0, t; }" : "=r"(sb) : "l"(smem));

    const int nmy = (cta < NMY_THRESH) ? 7 : 6;
    const int gtot = nmy * 4;

    float acc[8][4];
#pragma unroll
    for (int nt = 0; nt < 8; nt++)
#pragma unroll
        for (int e = 0; e < 4; e++) acc[nt][e] = 0.0f;

    // prologue: commit#0 = {A32(unit0), B chunk0}, commit#1 = {B chunk1}
    loadA32(sb, tid, x, cta);
    loadB(sb, tid, 0, 0);
    CP_COMMIT();
    loadB(sb, tid, 1, 1);
    CP_COMMIT();

    for (int g = 0; g < gtot; g++) {
        const int ci = g & 3;
        const int iu = g >> 2;
        if (g + 1 < gtot) { CP_WAIT(1); } else { CP_WAIT(0); }
        __syncthreads();

        if (ci == 0) {            // staging for this unit arrived in commit #g
            convertA(smem, tid);
            __syncthreads();
        }

        unsigned int aB = sb + SA16_OFF;
        unsigned int bB = sb + SB_OFF + (g & 1) * 65536;
        const int aSlice = ci * 8;   // chunk ci covers k-range [64ci, 64ci+64)
#pragma unroll
        for (int kk = 0; kk < 64; kk += 16) {
            unsigned int a[4], b[4][4];
            {
                int r = wm * 16 + (l & 15);
                int k16 = aSlice + (kk >> 3) + (l >> 4);
                unsigned int addr = aB + r * 512 + (((unsigned)(k16 ^ (r & 7))) << 4);
                LDSM4(a[0], a[1], a[2], a[3], addr);
            }
#pragma unroll
            for (int bn = 0; bn < 4; bn++) {
                int n = wn * 64 + bn * 16 + (l & 7) + ((l >> 4) & 1) * 8;
                int k16 = (kk >> 3) + ((l >> 3) & 1);
                unsigned int addr = bB + n * 128 + (((unsigned)(k16 ^ (n & 7))) << 4);
                LDSM4(b[bn][0], b[bn][1], b[bn][2], b[bn][3], addr);
            }
#pragma unroll
            for (int nt = 0; nt < 8; nt++)
                MMA16816(acc[nt], a, b[nt >> 1][(nt & 1) * 2], b[nt >> 1][(nt & 1) * 2 + 1]);
        }
        __syncthreads();   // buffers consumed; safe to refill

        int nx = g + 2;
        if (nx < gtot) {
            if ((nx & 3) == 0) loadA32(sb, tid, x, cta + (nx >> 2) * GRID);
            loadB(sb, tid, nx & 1, nx & 3);
            CP_COMMIT();
        }

        if (ci == 3) {
            // ---- epilogue for unit iu ----
            // col c = wn*64 + nt*8 + 2*(l&3) + e ; k = c & 255
            // k bits: b0=e(j7), b1..2=l&3(j6,j5), b3..5=nt(j4,j3,j2), b6=wn&1(j1), b7=(wn>>1)&1(j0)
            const int unit = cta + iu * GRID;
            float yp[2][8];
#pragma unroll
            for (int half = 0; half < 2; half++) {
                float s0 = 0.f, T7 = 0.f, T4 = 0.f, T3 = 0.f, T2 = 0.f;
#pragma unroll
                for (int nt = 0; nt < 8; nt++) {
                    float v0 = acc[nt][2 * half];
                    float v1 = acc[nt][2 * half + 1];
                    float p1 = v1 * v1;
                    float ps = v0 * v0 + p1;
                    s0 += ps; T7 += p1;
                    if (nt & 1) T4 += ps;
                    if (nt & 2) T3 += ps;
                    if (nt & 4) T2 += ps;
                }
                yp[half][7] = s0 - 2.f * T7;
                yp[half][4] = s0 - 2.f * T4;
                yp[half][3] = s0 - 2.f * T3;
                yp[half][2] = s0 - 2.f * T2;
                yp[half][6] = (l & 1) ? -s0 : s0;
                yp[half][5] = (l & 2) ? -s0 : s0;
                yp[half][1] = (wn & 1) ? -s0 : s0;
                yp[half][0] = (wn & 2) ? -s0 : s0;
            }
#pragma unroll
            for (int off = 1; off <= 2; off <<= 1)
#pragma unroll
                for (int half = 0; half < 2; half++)
#pragma unroll
                    for (int ob = 0; ob < 8; ob++)
                        yp[half][ob] += __shfl_xor_sync(0xffffffffu, yp[half][ob], off);

            if ((l & 3) == 0) {
#pragma unroll
                for (int half = 0; half < 2; half++) {
                    int r = wm * 16 + half * 8 + (l >> 2);
                    float* dst = &ypart[((size_t)wn * 32 + r) * 8];
#pragma unroll
                    for (int ob = 0; ob < 8; ob++) dst[ob] = yp[half][ob];
                }
            }
            __syncthreads();

            if (tid < 256) {
                int row = tid >> 3, ob = tid & 7;
                float v = 0.f;
#pragma unroll
                for (int w = 0; w < 8; w++) v += ypart[((size_t)w * 32 + row) * 8 + ob];
                yout[tid] = v;
            }
            __syncthreads();
            if (tid < 32) {
                float yv[8], n2 = 0.f;
#pragma unroll
                for (int ob = 0; ob < 8; ob++) { yv[ob] = yout[tid * 8 + ob]; n2 += yv[ob] * yv[ob]; }
                float inv = 1.0f / fmaxf(n2, 1e-30f);
#pragma unroll
                for (int ob = 0; ob < 8; ob++) yout[tid * 8 + ob] = yv[ob] * yv[ob] * inv;
            }
            __syncthreads();
            // write 32 rows x 64 float4 (only q<2 nonzero)
#pragma unroll
            for (int i = 0; i < 4; i++) {
                int idx = tid + i * THREADS;
                int rr = idx >> 6, q = idx & 63;
                float4 v = make_float4(0.f, 0.f, 0.f, 0.f);
                if (q == 0)      v = *reinterpret_cast<float4*>(&yout[rr * 8]);
                else if (q == 1) v = *reinterpret_cast<float4*>(&yout[rr * 8 + 4]);
                reinterpret_cast<float4*>(out + (size_t)(unit * 32 + rr) * 256)[q] = v;
            }
            __syncthreads();   // ypart/yout free before next unit's epilogue

#pragma unroll
            for (int nt = 0; nt < 8; nt++)
#pragma unroll
                for (int e = 0; e < 4; e++) acc[nt][e] = 0.0f;
        }
    }
}

extern "C" void kernel_launch(void* const* d_in, const int* in_sizes, int n_in,
                              void* d_out, int out_size) {
    const float* x   = (const float*)d_in[0];
    const float* th1 = (const float*)d_in[1];
    const float* th2 = (const float*)d_in[2];
    const float* th3 = (const float*)d_in[3];
    float* out = (float*)d_out;

    (void)in_sizes; (void)n_in; (void)out_size;

    cudaFuncSetAttribute(pqc_gemm_kernel,
                         cudaFuncAttributeMaxDynamicSharedMemorySize, SMEM_TOT);

    build_kernel<<<32, 256>>>(th1, th2, th3);
    pqc_gemm_kernel<<<GRID, THREADS, SMEM_TOT>>>(x, out);
}